// round 17
// baseline (speedup 1.0000x reference)
#include <cuda_runtime.h>
#include <cuda_fp16.h>
#include <math.h>
#include <stdint.h>

#define BATCH 4
#define SEQ   2048
#define HID   1024
#define MTOT  (BATCH * SEQ)   // 8192
#define SCALE (1.0f / 32.0f)  // 1/sqrt(1024)

// ---------------------------------------------------------------------------
// Scratch (device globals; allocation-free per harness rules)
// ---------------------------------------------------------------------------
__device__ __half g_Xh[(size_t)MTOT * HID];

__device__ __half g_Wqr[HID * HID];    // Wq raw (row-major), fp16
__device__ __half g_Wkr[HID * HID];    // Wk raw (row-major), fp16
__device__ __half g_Wvh[HID * HID];    // Wv^T, fp16
__device__ __half g_Whh[HID * HID];    // Wh^T, fp16

__device__ float  g_MTp[(size_t)4 * HID * HID];  // split-K partials (fp32)
__device__ __half g_MT[HID * HID];     // MT = Wk @ Wq^T, fp16
__device__ float  g_w2[HID];           // w2 = Wk @ bq
__device__ float  g_v[MTOT];           // v = (X @ w2) / 32

__device__ __half g_Ah[(size_t)MTOT * HID];       // A = X @ M (fp16)
__device__ __half g_Vth[(size_t)MTOT * HID];      // per-batch [HID, SEQ]

__device__ __half g_Ssc[(size_t)BATCH * SEQ * SEQ];  // raw scores (fp16)
__device__ __half g_Sh[(size_t)BATCH * SEQ * SEQ];   // softmax probs (fp16)

__device__ __half g_Ch[(size_t)MTOT * HID];

// ---------------------------------------------------------------------------
// helpers
// ---------------------------------------------------------------------------
__device__ __forceinline__ uint32_t smem_u32(const void* p) {
    uint32_t a;
    asm("{ .reg .u64 t; cvta.to.shared.u64 t, %1; cvt.u32.u64 %0, t; }"
        : "=r"(a) : "l"(p));
    return a;
}

__device__ __forceinline__ void cp16(uint32_t saddr, const void* gaddr) {
    asm volatile("cp.async.cg.shared.global [%0], [%1], 16;"
                 :: "r"(saddr), "l"(gaddr));
}
__device__ __forceinline__ void cp_commit() {
    asm volatile("cp.async.commit_group;" ::: "memory");
}
template <int N>
__device__ __forceinline__ void cp_wait() {
    asm volatile("cp.async.wait_group %0;" :: "n"(N) : "memory");
}

__device__ __forceinline__ void ldsm4(uint32_t addr, uint32_t& r0, uint32_t& r1,
                                      uint32_t& r2, uint32_t& r3) {
    asm volatile("ldmatrix.sync.aligned.m8n8.x4.shared.b16 {%0,%1,%2,%3}, [%4];"
                 : "=r"(r0), "=r"(r1), "=r"(r2), "=r"(r3) : "r"(addr));
}

__device__ __forceinline__ void mma16816(float* c, const uint32_t* a,
                                         uint32_t b0, uint32_t b1) {
    asm volatile(
        "mma.sync.aligned.m16n8k16.row.col.f32.f16.f16.f32 "
        "{%0,%1,%2,%3}, {%4,%5,%6,%7}, {%8,%9}, {%0,%1,%2,%3};"
        : "+f"(c[0]), "+f"(c[1]), "+f"(c[2]), "+f"(c[3])
        : "r"(a[0]), "r"(a[1]), "r"(a[2]), "r"(a[3]), "r"(b0), "r"(b1));
}

// ldmatrix x4 source address inside a [128 rows x 128B] swizzled tile.
__device__ __forceinline__ uint32_t lds_addr128(uint32_t tb, int base_row, int ks, int lane) {
    int r = base_row + ((lane >> 3) & 1) * 8 + (lane & 7);
    int c = (ks * 2 + (lane >> 4)) ^ (r & 7);
    return tb + (uint32_t)(r * 128 + c * 16);
}

// ---------------------------------------------------------------------------
// fp16 NT GEMM (fp32 accum): C[M,N] = alpha*(A @ B^T) + bias
//   A:[M,*] fp16, ld = row stride (elements); K = reduction extent;
//   B:[N,*] fp16 same ld; z-strides for A/B/C/bias (sA/sB in ELEMENTS).
// Block 128x128, Ktile 64, **4 warps (128 thr), 64x64 warp tile**:
// per ks-step 8 ldsm.x4 feed 32 MMAs (128B smem/MMA, was 250B) — halves
// SMEM crossbar traffic per MMA, which R16 analysis showed is the binding
// constraint (crossbar 2048cyc vs tensor 1024cyc per ktile-pair => 50%).
// 3-stage cp.async ring, SAFE order: wait -> sync -> issue -> compute.
// OUTMODE: 0 = fp32, 1 = fp16.  BIAS: 0 = none, 1 = per-col, 2 = per-row.
// ---------------------------------------------------------------------------
#define STAGE_BYTES 32768u   // A 16KB + B 16KB
#define GEMM_SMEM   98304    // 3 stages
#define GEMM_THREADS 128

template <int OUTMODE, int BIAS>
__global__ __launch_bounds__(GEMM_THREADS) void gemm_h(
    const __half* __restrict__ Ap, const __half* __restrict__ Bp,
    const float* __restrict__ bias,
    float* __restrict__ Cf, __half* __restrict__ Ch,
    int N, int K, int ld,
    size_t sA, size_t sB, size_t sC, size_t sBias, float alpha)
{
    extern __shared__ char smem_raw[];
    const uint32_t smem = smem_u32(smem_raw);

    const int tid  = threadIdx.x;
    const int lane = tid & 31;
    const int warp = tid >> 5;         // 0..3
    const int wm = warp >> 1;          // 0..1  (M)
    const int wn = warp & 1;           // 0..1  (N)
    const int bn = blockIdx.x, bm = blockIdx.y, z = blockIdx.z;

    const __half* pA = Ap + (size_t)z * sA + (size_t)bm * 128 * ld;
    const __half* pB = Bp + (size_t)z * sB + (size_t)bn * 128 * ld;
    if (BIAS) bias += (size_t)z * sBias;

    // 128 threads: 1024 chunks/tile -> 8 chunks/thread/tile
    auto stage_load = [&](uint32_t sb, int k0) {
#pragma unroll
        for (int h = 0; h < 8; ++h) {
            const int ch  = tid + h * GEMM_THREADS;   // 0..1023
            const int row = ch >> 3, c = ch & 7;
            const int cs  = c ^ (row & 7);
            const uint32_t so = (uint32_t)(row * 128 + cs * 16);
            const size_t   go = (size_t)row * ld + k0 + c * 8;
            cp16(sb +     0 + so, pA + go);
            cp16(sb + 16384 + so, pB + go);
        }
    };

    float acc[4][8][4];
#pragma unroll
    for (int i = 0; i < 4; ++i)
#pragma unroll
        for (int j = 0; j < 8; ++j)
#pragma unroll
            for (int q = 0; q < 4; ++q) acc[i][j][q] = 0.f;

    const int KT = K >> 6;

    // prologue: stages 0 and 1 in flight (2 groups)
    stage_load(smem, 0);
    cp_commit();
    if (KT > 1) stage_load(smem + STAGE_BYTES, 64);
    cp_commit();

    int buf = 0;   // buffer of stage kt
    for (int kt = 0; kt < KT; ++kt) {
        cp_wait<1>();        // stage kt landed
        __syncthreads();     // all warps done reading buffer to be refilled

        if (kt + 2 < KT) {
            int nb = buf + 2; if (nb >= 3) nb -= 3;
            stage_load(smem + (uint32_t)nb * STAGE_BYTES, (kt + 2) * 64);
        }
        cp_commit();

        const uint32_t sb = smem + (uint32_t)buf * STAGE_BYTES;
#pragma unroll
        for (int ks = 0; ks < 4; ++ks) {
            uint32_t aH[4][4], bH[8][2];
#pragma unroll
            for (int i = 0; i < 4; ++i)
                ldsm4(lds_addr128(sb, wm * 64 + i * 16, ks, lane),
                      aH[i][0], aH[i][1], aH[i][2], aH[i][3]);
#pragma unroll
            for (int j2 = 0; j2 < 4; ++j2) {
                uint32_t r0, r1, r2, r3;
                ldsm4(lds_addr128(sb + 16384, wn * 64 + j2 * 16, ks, lane), r0, r1, r2, r3);
                bH[j2 * 2 + 0][0] = r0; bH[j2 * 2 + 0][1] = r2;
                bH[j2 * 2 + 1][0] = r1; bH[j2 * 2 + 1][1] = r3;
            }
#pragma unroll
            for (int i = 0; i < 4; ++i)
#pragma unroll
                for (int j = 0; j < 8; ++j)
                    mma16816(acc[i][j], aH[i], bH[j][0], bH[j][1]);
        }
        if (++buf == 3) buf = 0;
    }

    // epilogue: warp covers rows [wm*64, wm*64+64), cols [wn*64, wn*64+64)
    const size_t growb = (size_t)bm * 128 + wm * 64;
    const int    gcolb = bn * 128 + wn * 64;
#pragma unroll
    for (int i = 0; i < 4; ++i) {
        const size_t r0 = growb + i * 16 + (lane >> 2);
        float br0 = 0.f, br1 = 0.f;
        if (BIAS == 2) { br0 = bias[r0]; br1 = bias[r0 + 8]; }
#pragma unroll
        for (int j = 0; j < 8; ++j) {
            const int col = gcolb + j * 8 + (lane & 3) * 2;
            float c0 = 0.f, c1 = 0.f;
            if (BIAS == 1) { c0 = bias[col]; c1 = bias[col + 1]; }
            const float v00 = acc[i][j][0] * alpha + (BIAS == 2 ? br0 : c0);
            const float v01 = acc[i][j][1] * alpha + (BIAS == 2 ? br0 : c1);
            const float v10 = acc[i][j][2] * alpha + (BIAS == 2 ? br1 : c0);
            const float v11 = acc[i][j][3] * alpha + (BIAS == 2 ? br1 : c1);
            const size_t o0 = (size_t)z * sC + r0 * N + col;
            const size_t o1 = o0 + (size_t)8 * N;
            if (OUTMODE == 0) {
                *reinterpret_cast<float2*>(Cf + o0) = make_float2(v00, v01);
                *reinterpret_cast<float2*>(Cf + o1) = make_float2(v10, v11);
            } else {
                *reinterpret_cast<__half2*>(Ch + o0) =
                    __halves2half2(__float2half_rn(v00), __float2half_rn(v01));
                *reinterpret_cast<__half2*>(Ch + o1) =
                    __halves2half2(__float2half_rn(v10), __float2half_rn(v11));
            }
        }
    }
}

// ---------------------------------------------------------------------------
// Weight prep (z selects): z=0 Wq raw->fp16, z=1 Wk raw->fp16,
// z=2 Wv transpose->fp16, z=3 Wh transpose->fp16.
// ---------------------------------------------------------------------------
__global__ __launch_bounds__(256) void convert_weights(
    const float* __restrict__ W0, const float* __restrict__ W1,
    const float* __restrict__ W2, const float* __restrict__ W3,
    __half* __restrict__ H0, __half* __restrict__ H1,
    __half* __restrict__ H2, __half* __restrict__ H3)
{
    __shared__ float t[32][33];
    const int zi = blockIdx.z;
    const float* in = (zi == 0) ? W0 : (zi == 1) ? W1 : (zi == 2) ? W2 : W3;
    __half* hO = (zi == 0) ? H0 : (zi == 1) ? H1 : (zi == 2) ? H2 : H3;

    const int r0 = blockIdx.y * 32, c0 = blockIdx.x * 32;
    const int tx = threadIdx.x, ty = threadIdx.y;   // (32, 8)
#pragma unroll
    for (int j = 0; j < 4; ++j)
        t[ty + 8 * j][tx] = in[(size_t)(r0 + ty + 8 * j) * HID + c0 + tx];
    __syncthreads();
    if (zi < 2) {
#pragma unroll
        for (int j = 0; j < 4; ++j) {
            size_t o = (size_t)(r0 + ty + 8 * j) * HID + c0 + tx;
            hO[o] = __float2half_rn(t[ty + 8 * j][tx]);
        }
    } else {
#pragma unroll
        for (int j = 0; j < 4; ++j) {
            size_t o = (size_t)(c0 + ty + 8 * j) * HID + r0 + tx;
            hO[o] = __float2half_rn(t[tx][ty + 8 * j]);
        }
    }
}

// ---------------------------------------------------------------------------
// Reduce split-K partials: MT = fp16(p0 + p1 + p2 + p3), vectorized by 4
// ---------------------------------------------------------------------------
__global__ __launch_bounds__(256) void reduce_mt(
    const float* __restrict__ p, __half* __restrict__ mt)
{
    const size_t S = (size_t)HID * HID;
    size_t i = ((size_t)blockIdx.x * 256 + threadIdx.x) * 4;
    float4 a = *reinterpret_cast<const float4*>(p + i);
    float4 b = *reinterpret_cast<const float4*>(p + S + i);
    float4 c = *reinterpret_cast<const float4*>(p + 2 * S + i);
    float4 d = *reinterpret_cast<const float4*>(p + 3 * S + i);
    __align__(8) __half hb[4];
    hb[0] = __float2half_rn(a.x + b.x + c.x + d.x);
    hb[1] = __float2half_rn(a.y + b.y + c.y + d.y);
    hb[2] = __float2half_rn(a.z + b.z + c.z + d.z);
    hb[3] = __float2half_rn(a.w + b.w + c.w + d.w);
    *reinterpret_cast<uint2*>(mt + i) = *reinterpret_cast<uint2*>(hb);
}

// ---------------------------------------------------------------------------
// w2[k] = sum_i Wk[k][i] * bq[i]  (one block per k)
// ---------------------------------------------------------------------------
__global__ __launch_bounds__(256) void gemv_w2(
    const float* __restrict__ Wk, const float* __restrict__ bq,
    float* __restrict__ w2)
{
    const int k = blockIdx.x, tid = threadIdx.x;
    float s = 0.f;
#pragma unroll
    for (int q = 0; q < 4; ++q) {
        int i = tid + q * 256;
        s += Wk[(size_t)k * HID + i] * bq[i];
    }
    __shared__ float red[256];
    red[tid] = s;
    __syncthreads();
#pragma unroll
    for (int st = 128; st > 0; st >>= 1) {
        if (tid < st) red[tid] += red[tid + st];
        __syncthreads();
    }
    if (tid == 0) w2[k] = red[0];
}

// ---------------------------------------------------------------------------
// X row -> fp16 + v[m] = (X_m . w2) * SCALE.  One block per row.
// ---------------------------------------------------------------------------
__global__ __launch_bounds__(256) void to_half_v(
    const float* __restrict__ X, const float* __restrict__ w2,
    __half* __restrict__ Xh, float* __restrict__ v)
{
    const int m = blockIdx.x, tid = threadIdx.x;
    const size_t base = (size_t)m * HID;
    float4 val = reinterpret_cast<const float4*>(X + base)[tid];

    __align__(8) __half hb[4];
    hb[0] = __float2half_rn(val.x);
    hb[1] = __float2half_rn(val.y);
    hb[2] = __float2half_rn(val.z);
    hb[3] = __float2half_rn(val.w);
    reinterpret_cast<uint2*>(Xh + base)[tid] = *reinterpret_cast<uint2*>(hb);

    const float4 wv = reinterpret_cast<const float4*>(w2)[tid];
    float s = val.x * wv.x + val.y * wv.y + val.z * wv.z + val.w * wv.w;
    __shared__ float red[256];
    red[tid] = s;
    __syncthreads();
#pragma unroll
    for (int st = 128; st > 0; st >>= 1) {
        if (tid < st) red[tid] += red[tid + st];
        __syncthreads();
    }
    if (tid == 0) v[m] = red[0] * SCALE;
}

// ---------------------------------------------------------------------------
// Row softmax over 2048 cols, fp16 in, fp16 out (fp32 internal).
// ---------------------------------------------------------------------------
__global__ __launch_bounds__(256) void softmax_h(
    const __half* __restrict__ Ssc, __half* __restrict__ Sh)
{
    const size_t base = (size_t)blockIdx.x * SEQ;
    const int tid = threadIdx.x;
    const __half2* in2 = reinterpret_cast<const __half2*>(Ssc + base);
    __half2* out2 = reinterpret_cast<__half2*>(Sh + base);

    float v[8];
    float m = -INFINITY;
#pragma unroll
    for (int i = 0; i < 4; ++i) {
        float2 p = __half22float2(in2[tid + i * 256]);
        v[2 * i] = p.x; v[2 * i + 1] = p.y;
        m = fmaxf(m, fmaxf(p.x, p.y));
    }

    __shared__ float red[256];
    red[tid] = m;
    __syncthreads();
#pragma unroll
    for (int s = 128; s > 0; s >>= 1) {
        if (tid < s) red[tid] = fmaxf(red[tid], red[tid + s]);
        __syncthreads();
    }
    m = red[0];
    __syncthreads();

    float sum = 0.f;
#pragma unroll
    for (int i = 0; i < 8; ++i) {
        v[i] = expf(v[i] - m);
        sum += v[i];
    }
    red[tid] = sum;
    __syncthreads();
#pragma unroll
    for (int s = 128; s > 0; s >>= 1) {
        if (tid < s) red[tid] += red[tid + s];
        __syncthreads();
    }
    const float inv = 1.0f / red[0];
#pragma unroll
    for (int i = 0; i < 4; ++i)
        out2[tid + i * 256] = __floats2half2_rn(v[2 * i] * inv, v[2 * i + 1] * inv);
}

// ---------------------------------------------------------------------------
extern "C" void kernel_launch(void* const* d_in, const int* in_sizes, int n_in,
                              void* d_out, int out_size)
{
    (void)in_sizes; (void)n_in; (void)out_size;

    const float* X  = (const float*)d_in[0];
    const float* Wq = (const float*)d_in[1];
    const float* bq = (const float*)d_in[2];
    const float* Wk = (const float*)d_in[3];
    const float* bk = (const float*)d_in[4];   // cancels in softmax (row-const)
    const float* Wv = (const float*)d_in[5];
    const float* bv = (const float*)d_in[6];
    const float* Wh = (const float*)d_in[7];
    const float* bh = (const float*)d_in[8];
    float* out = (float*)d_out;
    (void)bk;

    __half *Xh, *Wqr, *Wkr, *Wvh, *Whh, *MT, *Ah, *Vth, *Ssc, *Sh, *Ch;
    float *MTp, *w2, *v;
    cudaGetSymbolAddress((void**)&Xh,  g_Xh);
    cudaGetSymbolAddress((void**)&Wqr, g_Wqr);
    cudaGetSymbolAddress((void**)&Wkr, g_Wkr);
    cudaGetSymbolAddress((void**)&Wvh, g_Wvh);
    cudaGetSymbolAddress((void**)&Whh, g_Whh);
    cudaGetSymbolAddress((void**)&MTp, g_MTp);
    cudaGetSymbolAddress((void**)&MT,  g_MT);
    cudaGetSymbolAddress((void**)&w2,  g_w2);
    cudaGetSymbolAddress((void**)&v,   g_v);
    cudaGetSymbolAddress((void**)&Ah,  g_Ah);
    cudaGetSymbolAddress((void**)&Vth, g_Vth);
    cudaGetSymbolAddress((void**)&Ssc, g_Ssc);
    cudaGetSymbolAddress((void**)&Sh,  g_Sh);
    cudaGetSymbolAddress((void**)&Ch,  g_Ch);

    cudaFuncSetAttribute(gemm_h<0,0>, cudaFuncAttributeMaxDynamicSharedMemorySize, GEMM_SMEM);
    cudaFuncSetAttribute(gemm_h<0,1>, cudaFuncAttributeMaxDynamicSharedMemorySize, GEMM_SMEM);
    cudaFuncSetAttribute(gemm_h<1,0>, cudaFuncAttributeMaxDynamicSharedMemorySize, GEMM_SMEM);
    cudaFuncSetAttribute(gemm_h<1,1>, cudaFuncAttributeMaxDynamicSharedMemorySize, GEMM_SMEM);
    cudaFuncSetAttribute(gemm_h<1,2>, cudaFuncAttributeMaxDynamicSharedMemorySize, GEMM_SMEM);

    const dim3 blk(256);
    const dim3 gblk(GEMM_THREADS);

    // L0: weight prep (Wq/Wk raw fp16; Wv/Wh transposed fp16)
    dim3 tgw(HID / 32, HID / 32, 4), tblk(32, 8);
    convert_weights<<<tgw, tblk>>>(Wq, Wk, Wv, Wh, Wqr, Wkr, Wvh, Whh);

    // L1: MT partials = Wk @ Wq^T, split-K over z (K=256 each) -> fp32
    dim3 gm(HID / 128, HID / 128, 4);
    gemm_h<0,0><<<gm, gblk, GEMM_SMEM>>>(Wkr, Wqr, nullptr, MTp, nullptr,
                                         HID, 256, HID,
                                         256, 256, (size_t)HID * HID, 0, 1.f);

    // L2: MT = fp16(sum of partials)
    reduce_mt<<<HID * HID / 1024, blk>>>(MTp, MT);

    // L3: w2 = Wk @ bq
    gemv_w2<<<HID, blk>>>(Wk, bq, w2);

    // L4: X -> fp16 + v = (X @ w2) * scale
    to_half_v<<<MTOT, blk>>>(X, w2, Xh, v);

    // L5: V^T = Wv^T @ X^T (per batch), ROW bias, fp16 out
    dim3 gv(SEQ / 128, HID / 128, BATCH);
    gemm_h<1,2><<<gv, gblk, GEMM_SMEM>>>(Wvh, Xh, bv, nullptr, Vth,
                                         SEQ, HID, HID,
                                         0, (size_t)SEQ * HID, (size_t)HID * SEQ,
                                         0, 1.f);

    // L6: A = X @ MT^T  (fp16 out)
    dim3 ga(HID / 128, MTOT / 128, 1);
    gemm_h<1,0><<<ga, gblk, GEMM_SMEM>>>(Xh, MT, nullptr, nullptr, Ah,
                                         HID, HID, HID, 0, 0, 0, 0, 1.f);

    // L7: scores = scale * (A @ X^T) + v_col (batched; u,c cancel in softmax)
    dim3 gs(SEQ / 128, SEQ / 128, BATCH);
    gemm_h<1,1><<<gs, gblk, GEMM_SMEM>>>(Ah, Xh, v, nullptr, Ssc,
                                         SEQ, HID, HID,
                                         (size_t)SEQ * HID, (size_t)SEQ * HID,
                                         (size_t)SEQ * SEQ, SEQ, SCALE);

    // L8: softmax fp16 -> fp16
    softmax_h<<<BATCH * SEQ, blk>>>(Ssc, Sh);

    // L9: context = attn @ V (batched, K=2048) -> fp16
    dim3 gc(HID / 128, SEQ / 128, BATCH);
    gemm_h<1,0><<<gc, gblk, GEMM_SMEM>>>(Sh, Vth, nullptr, nullptr, Ch,
                                         HID, SEQ, SEQ,
                                         (size_t)SEQ * SEQ, (size_t)HID * SEQ,
                                         (size_t)SEQ * HID, 0, 1.f);

    // L10: y = context @ Wh + bh -> d_out fp32
    dim3 go(HID / 128, MTOT / 128, 1);
    gemm_h<0,1><<<go, gblk, GEMM_SMEM>>>(Ch, Whh, bh, out, nullptr,
                                         HID, HID, HID, 0, 0, 0, 0, 1.f);
}